// round 3
// baseline (speedup 1.0000x reference)
#include <cuda_runtime.h>
#include <math.h>

#define NQ 256
#define ND 256
#define NI 2048
#define SE_INV_TEMP 5.0f
#define BN_EPS 1e-5f

// ---- scratch (no allocations allowed) ----
__device__ float g_A1[NQ * ND];   // u_hat * w
__device__ float g_A2[NQ * ND];   // w * w
__device__ float g_A3[NQ * ND];   // 2 * w * b
__device__ float g_c1[NQ];        // u_hat . b
__device__ float g_B;             // sum b^2
__device__ float g_yg[NI * ND];   // l2-normalized gallery
__device__ float g_yg2[NI * ND];  // its elementwise square

// Block-wide sum over 256 threads.
__device__ __forceinline__ float blockReduceSum256(float v, float* sred) {
    int lane = threadIdx.x & 31;
    int w = threadIdx.x >> 5;
#pragma unroll
    for (int o = 16; o > 0; o >>= 1) v += __shfl_xor_sync(0xffffffffu, v, o);
    if (lane == 0) sred[w] = v;
    __syncthreads();
    float tot = 0.f;
#pragma unroll
    for (int j = 0; j < 8; ++j) tot += sred[j];
    __syncthreads();
    return tot;
}

// ---- Kernel A: normalize gallery rows, produce yg and yg^2 ----
__global__ __launch_bounds__(256) void gallery_prep(const float* __restrict__ gal) {
    __shared__ float sred[8];
    int i = blockIdx.x;
    int d = threadIdx.x;
    float v = gal[i * ND + d];
    float ss = blockReduceSum256(v * v, sred);
    float r = 1.f / fmaxf(sqrtf(ss), 1e-12f);
    float yh = v * r;
    g_yg[i * ND + d] = yh;
    g_yg2[i * ND + d] = yh * yh;
}

// ---- Kernel B: per-query precompute of A1/A2/A3, c1, B ----
__global__ __launch_bounds__(256) void query_prep(
    const float* __restrict__ qf, const float* __restrict__ qif,
    const float* __restrict__ gamma, const float* __restrict__ beta,
    const float* __restrict__ mean, const float* __restrict__ var) {
    __shared__ float sred[8];
    int q = blockIdx.x;
    int d = threadIdx.x;

    float s = gamma[d] * rsqrtf(var[d] + BN_EPS);
    float bb = beta[d] - mean[d] * s;

    float x = qf[q * ND + d];
    float nx = blockReduceSum256(x * x, sred);
    float xh = x / fmaxf(sqrtf(nx), 1e-12f);
    float gate = 1.f / (1.f + __expf(-xh * SE_INV_TEMP));

    float y = qif[q * ND + d];
    float ny = blockReduceSum256(y * y, sred);
    float yh = y / fmaxf(sqrtf(ny), 1e-12f);

    float w = gate * s;
    float u = yh * w + bb;                    // fused_query (pre-norm)
    float nu = blockReduceSum256(u * u, sred);
    float uh = u / fmaxf(sqrtf(nu), 1e-12f);

    g_A1[q * ND + d] = uh * w;
    g_A2[q * ND + d] = w * w;
    g_A3[q * ND + d] = 2.f * w * bb;

    float c1 = blockReduceSum256(uh * bb, sred);
    if (d == 0) g_c1[q] = c1;
    if (q == 0) {
        float Bs = blockReduceSum256(bb * bb, sred);
        if (d == 0) g_B = Bs;
    }
}

// ---- Kernel C: fused triple GEMM + sigmoid epilogue ----
// scores[q,i] = sigmoid((yg.A1 + c1) * rsqrt(yg2.A2 + yg.A3 + B))
#define TI 64
#define TQ 64
#define KC 32
#define LDSH 68  // float stride: 16B-aligned, bank-staggered (68 % 32 = 4)

__global__ __launch_bounds__(256) void score_main(float* __restrict__ out) {
    __shared__ float sYG[KC * LDSH];
    __shared__ float sYG2[KC * LDSH];
    __shared__ float sA1[KC * LDSH];
    __shared__ float sA2[KC * LDSH];
    __shared__ float sA3[KC * LDSH];

    const int iBase = blockIdx.x * TI;
    const int qBase = blockIdx.y * TQ;
    const int tid = threadIdx.x;

    // staging mapping: 32 rows x 8 k-quads per pass, 2 passes of rows
    const int sr = tid >> 3;         // 0..31
    const int skq = (tid & 7) * 4;   // 0,4,...,28

    // compute mapping: 16 x 16 threads, 4x4 micro-tile
    const int i0 = (tid & 15) * 4;
    const int q0 = (tid >> 4) * 4;

    float accN[4][4];
    float accD[4][4];
#pragma unroll
    for (int a = 0; a < 4; ++a)
#pragma unroll
        for (int b = 0; b < 4; ++b) { accN[a][b] = 0.f; accD[a][b] = 0.f; }

    for (int k0 = 0; k0 < ND; k0 += KC) {
        __syncthreads();  // previous compute done before overwrite
#pragma unroll
        for (int p = 0; p < 2; ++p) {
            int row = sr + p * 32;
            float4 vg  = *(const float4*)&g_yg [(iBase + row) * ND + k0 + skq];
            float4 vg2 = *(const float4*)&g_yg2[(iBase + row) * ND + k0 + skq];
            float4 v1  = *(const float4*)&g_A1 [(qBase + row) * ND + k0 + skq];
            float4 v2  = *(const float4*)&g_A2 [(qBase + row) * ND + k0 + skq];
            float4 v3  = *(const float4*)&g_A3 [(qBase + row) * ND + k0 + skq];
            const float* pg  = &vg.x;
            const float* pg2 = &vg2.x;
            const float* p1  = &v1.x;
            const float* p2  = &v2.x;
            const float* p3  = &v3.x;
#pragma unroll
            for (int j = 0; j < 4; ++j) {
                sYG [(skq + j) * LDSH + row] = pg[j];
                sYG2[(skq + j) * LDSH + row] = pg2[j];
                sA1 [(skq + j) * LDSH + row] = p1[j];
                sA2 [(skq + j) * LDSH + row] = p2[j];
                sA3 [(skq + j) * LDSH + row] = p3[j];
            }
        }
        __syncthreads();

#pragma unroll
        for (int k = 0; k < KC; ++k) {
            float4 a  = *(const float4*)&sYG [k * LDSH + i0];
            float4 a2 = *(const float4*)&sYG2[k * LDSH + i0];
            float4 b1 = *(const float4*)&sA1 [k * LDSH + q0];
            float4 b2 = *(const float4*)&sA2 [k * LDSH + q0];
            float4 b3 = *(const float4*)&sA3 [k * LDSH + q0];
            const float* fa  = &a.x;
            const float* fa2 = &a2.x;
            const float* fb1 = &b1.x;
            const float* fb2 = &b2.x;
            const float* fb3 = &b3.x;
#pragma unroll
            for (int qq = 0; qq < 4; ++qq)
#pragma unroll
                for (int ii = 0; ii < 4; ++ii) {
                    accN[ii][qq] = fmaf(fa[ii], fb1[qq], accN[ii][qq]);
                    accD[ii][qq] = fmaf(fa2[ii], fb2[qq], accD[ii][qq]);
                    accD[ii][qq] = fmaf(fa[ii], fb3[qq], accD[ii][qq]);
                }
        }
    }

    float Bv = g_B;
    float c1v[4];
#pragma unroll
    for (int qq = 0; qq < 4; ++qq) c1v[qq] = g_c1[qBase + q0 + qq];

#pragma unroll
    for (int qq = 0; qq < 4; ++qq) {
        int qg = qBase + q0 + qq;
#pragma unroll
        for (int ii = 0; ii < 4; ++ii) {
            float num = accN[ii][qq] + c1v[qq];
            float den = accD[ii][qq] + Bv;
            float cosv = num * rsqrtf(fmaxf(den, 1e-24f));
            out[qg * NI + (iBase + i0 + ii)] = 1.f / (1.f + __expf(-cosv));
        }
    }
}

extern "C" void kernel_launch(void* const* d_in, const int* in_sizes, int n_in,
                              void* d_out, int out_size) {
    const float* query_feats = (const float*)d_in[0];
    const float* query_img_feats = (const float*)d_in[1];
    const float* gallery_img_feats = (const float*)d_in[2];
    const float* bn_gamma = (const float*)d_in[3];
    const float* bn_beta = (const float*)d_in[4];
    const float* bn_mean = (const float*)d_in[5];
    const float* bn_var = (const float*)d_in[6];
    float* out = (float*)d_out;

    gallery_prep<<<NI, 256>>>(gallery_img_feats);
    query_prep<<<NQ, 256>>>(query_feats, query_img_feats, bn_gamma, bn_beta,
                            bn_mean, bn_var);
    dim3 grid(NI / TI, NQ / TQ);
    score_main<<<grid, 256>>>(out);
}